// round 13
// baseline (speedup 1.0000x reference)
#include <cuda_runtime.h>
#include <math.h>

#define NRAYS   16384
#define NSAMP   128
#define TMASK   ((1u << 19) - 1u)
#define RPB     4                 // rays per block
#define NTHR    (128 * RPB)

extern "C" {
__device__ float  __nv_expf(float);
__device__ float  __nv_logf(float);
__device__ double __nv_exp(double);
}

// Big weight matrices in constant memory (uniform-datapath loads, off the L1 pipe):
// ws0 @0 (2048), ws1 @2048 (4096), wc1 @6144 (4096), wc2 @10240 (4096) = 56KB
#define COFF_WS0 0
#define COFF_WS1 2048
#define COFF_WC1 6144
#define COFF_WC2 10240
__constant__ float c_W[14336];

// Small weights in shared: ws2 @0 (1024), wc0 @1024 (1984), wc3 @3008 (192)
#define SOFF_WS2 0
#define SOFF_WC0 1024
#define SOFF_WC3 3008
#define SWTOT    3200

#define RAYBUF  288               // per-ray: alpha[128] w[128] red[32]
#define SMEM_FLOATS (SWTOT + RPB * RAYBUF)
#define SMEM_BYTES  (SMEM_FLOATS * 4)

__constant__ float c_res[16] = {16.f, 20.f, 25.f, 32.f, 40.f, 50.f, 64.f, 80.f,
                                101.f, 128.f, 161.f, 203.f, 256.f, 322.f, 406.f, 512.f};

typedef unsigned long long u64;

__device__ __forceinline__ u64 ffma2(u64 a, u64 b, u64 c) {
    u64 d;
    asm("fma.rn.f32x2 %0, %1, %2, %3;" : "=l"(d) : "l"(a), "l"(b), "l"(c));
    return d;
}
__device__ __forceinline__ u64 pack2(float v) {
    u64 d; unsigned r = __float_as_uint(v);
    asm("mov.b64 %0, {%1, %2};" : "=l"(d) : "r"(r), "r"(r));
    return d;
}
__device__ __forceinline__ void unpack2(u64 p, float& lo, float& hi) {
    asm("mov.b64 {%0, %1}, %2;" : "=f"(lo), "=f"(hi) : "l"(p));
}

// fl32(exp(-x)) for x >= 0, matching correctly-rounded fp32 exp bins.
__device__ __forceinline__ float exp32neg(float x) {
    if (x < 0.00048828125f) {               // 2^-11 (covers ~all samples)
        float t = __fmul_rn(x, x);
        float c = __fmaf_rn(x, -0.16666667f, 0.5f);   // 0.5 - x/6
        float y = __fmaf_rn(t, c, -x);                // -x + x^2/2 - x^3/6
        return __fadd_rn(1.0f, y);
    }
    if (x > 104.0f) return 0.0f;            // exp underflows to 0
    return (float)__nv_exp(-(double)x);     // rare middle band: exact fp64
}

// 64-output layer, two 32-output half-passes. Wb may point into c_W (constant
// space — uniform loads) or shared; accumulation order identical either way.
__device__ __forceinline__ void layer64(const float* __restrict__ Wb, int n_in,
                                        const float* __restrict__ in,
                                        float* __restrict__ outv, bool relu) {
    #pragma unroll 1
    for (int h = 0; h < 2; h++) {
        u64 acc2[16];
        #pragma unroll
        for (int k = 0; k < 16; k++) acc2[k] = 0ULL;
        #pragma unroll 1
        for (int i = 0; i < n_in; i++) {
            const u64 vv = pack2(in[i]);
            const ulonglong2* wr = reinterpret_cast<const ulonglong2*>(Wb + i * 64 + h * 32);
            #pragma unroll
            for (int q = 0; q < 8; q++) {
                ulonglong2 w2 = wr[q];
                acc2[2*q]   = ffma2(vv, w2.x, acc2[2*q]);
                acc2[2*q+1] = ffma2(vv, w2.y, acc2[2*q+1]);
            }
        }
        #pragma unroll
        for (int k = 0; k < 16; k++) {
            float lo, hi;
            unpack2(acc2[k], lo, hi);
            if (relu) { lo = fmaxf(lo, 0.0f); hi = fmaxf(hi, 0.0f); }
            outv[h * 32 + 2*k]     = lo;
            outv[h * 32 + 2*k + 1] = hi;
        }
    }
}

__global__ void __launch_bounds__(NTHR, 2)
nerf_fused(const float* __restrict__ rays,
           const float* __restrict__ tables,
           const float* __restrict__ ws2g,
           const float* __restrict__ wc0g,
           const float* __restrict__ wc3g,
           float* __restrict__ out)
{
    extern __shared__ float sm[];
    float* SW = sm;

    const int tid = threadIdx.x;
    const int r   = tid >> 7;         // ray slot in block
    const int s   = tid & 127;        // sample index
    const int ray = blockIdx.x * RPB + r;

    float* rb      = sm + SWTOT + r * RAYBUF;
    float* s_alpha = rb;              // 128
    float* s_w     = rb + 128;        // 128
    float* s_red   = rb + 256;        // 32 (4 used)

    // ---- stage the small weights into shared ----
    for (int i = tid; i < 1024; i += NTHR) SW[SOFF_WS2 + i] = ws2g[i];
    for (int i = tid; i < 1984; i += NTHR) SW[SOFF_WC0 + i] = wc0g[i];
    for (int i = tid; i < 192;  i += NTHR) SW[SOFF_WC3 + i] = wc3g[i];
    __syncthreads();

    // ---- ray / sample setup ----
    const float ox = rays[ray * 6 + 0];
    const float oy = rays[ray * 6 + 1];
    const float oz = rays[ray * 6 + 2];
    const float dx = rays[ray * 6 + 3];
    const float dy = rays[ray * 6 + 4];
    const float dz = rays[ray * 6 + 5];

    const float step = 4.0f / 127.0f;
    const float z     = __fadd_rn(2.0f, __fmul_rn(step, (float)s));
    const float znext = __fadd_rn(2.0f, __fmul_rn(step, (float)(s + 1)));

    const float px = __fadd_rn(ox, __fmul_rn(dx, z));
    const float py = __fadd_rn(oy, __fmul_rn(dy, z));
    const float pz = __fadd_rn(oz, __fmul_rn(dz, z));

    const float cx = fminf(fmaxf(px, -1.5f), 1.5f);
    const float cy = fminf(fmaxf(py, -1.5f), 1.5f);
    const float cz = fminf(fmaxf(pz, -1.5f), 1.5f);
    const bool keep = (px == cx) && (py == cy) && (pz == cz);

    // ---- multi-resolution hash encoding ----
    float featl[32];
    #pragma unroll 1
    for (int l = 0; l < 16; l++) {
        const float res  = c_res[l];
        const float grid = 3.0f / res;

        float tx = (cx - (-1.5f)) / grid;
        float ty = (cy - (-1.5f)) / grid;
        float tz = (cz - (-1.5f)) / grid;
        float fbx = floorf(tx), fby = floorf(ty), fbz = floorf(tz);
        float vmx = fbx * grid + (-1.5f);
        float vmy = fby * grid + (-1.5f);
        float vmz = fbz * grid + (-1.5f);
        float wx = (cx - vmx) / grid;
        float wy = (cy - vmy) / grid;
        float wz = (cz - vmz) / grid;

        unsigned bx = (unsigned)(int)fbx;
        unsigned by = (unsigned)(int)fby;
        unsigned bz = (unsigned)(int)fbz;

        unsigned hx0 = bx, hx1 = bx + 1u;
        unsigned hy0 = by * 2654435761u, hy1 = (by + 1u) * 2654435761u;
        unsigned hz0 = bz * 805459861u,  hz1 = (bz + 1u) * 805459861u;

        const float2* tab = reinterpret_cast<const float2*>(tables) + ((size_t)l << 19);
        float2 e000 = __ldg(&tab[(hx0 ^ hy0 ^ hz0) & TMASK]);
        float2 e001 = __ldg(&tab[(hx0 ^ hy0 ^ hz1) & TMASK]);
        float2 e010 = __ldg(&tab[(hx0 ^ hy1 ^ hz0) & TMASK]);
        float2 e011 = __ldg(&tab[(hx0 ^ hy1 ^ hz1) & TMASK]);
        float2 e100 = __ldg(&tab[(hx1 ^ hy0 ^ hz0) & TMASK]);
        float2 e101 = __ldg(&tab[(hx1 ^ hy0 ^ hz1) & TMASK]);
        float2 e110 = __ldg(&tab[(hx1 ^ hy1 ^ hz0) & TMASK]);
        float2 e111 = __ldg(&tab[(hx1 ^ hy1 ^ hz1) & TMASK]);

        const float u0 = 1.0f - wx, u1 = 1.0f - wy, u2 = 1.0f - wz;
        float c00a = e000.x * u0 + e100.x * wx, c00b = e000.y * u0 + e100.y * wx;
        float c01a = e001.x * u0 + e101.x * wx, c01b = e001.y * u0 + e101.y * wx;
        float c10a = e010.x * u0 + e110.x * wx, c10b = e010.y * u0 + e110.y * wx;
        float c11a = e011.x * u0 + e111.x * wx, c11b = e011.y * u0 + e111.y * wx;
        float c0a = c00a * u1 + c10a * wy, c0b = c00b * u1 + c10b * wy;
        float c1a = c01a * u1 + c11a * wy, c1b = c01b * u1 + c11b * wy;
        featl[l * 2 + 0] = c0a * u2 + c1a * wz;
        featl[l * 2 + 1] = c0b * u2 + c1b * wz;
    }

    // ---- sigma MLP: 32 -> 64 -> 64 -> 16 ----
    float actl[64];
    layer64(c_W + COFF_WS0, 32, featl, actl, true);
    {
        float tmp[64];
        layer64(c_W + COFF_WS1, 64, actl, tmp, true);
        #pragma unroll
        for (int j = 0; j < 64; j++) actl[j] = tmp[j];
    }
    float h3[16];
    {   // 64 -> 16 (ws2, shared)
        u64 acc2[8];
        #pragma unroll
        for (int k = 0; k < 8; k++) acc2[k] = 0ULL;
        #pragma unroll 1
        for (int i = 0; i < 64; i++) {
            const u64 vv = pack2(actl[i]);
            const ulonglong2* wr = reinterpret_cast<const ulonglong2*>(SW + SOFF_WS2 + i * 16);
            #pragma unroll
            for (int q = 0; q < 4; q++) {
                ulonglong2 w2 = wr[q];
                acc2[2*q]   = ffma2(vv, w2.x, acc2[2*q]);
                acc2[2*q+1] = ffma2(vv, w2.y, acc2[2*q+1]);
            }
        }
        #pragma unroll
        for (int k = 0; k < 8; k++) unpack2(acc2[k], h3[2*k], h3[2*k+1]);
    }
    float sigma = h3[0];

    // ---- SH + geo -> color input (31) ----
    float cin[31];
    {
        const float x = dx, y = dy, zc = dz;
        const float xx = x * x, yy = y * y, zz = zc * zc;
        const float xy = x * y, yz = y * zc, xz = x * zc;
        cin[0]  = 0.28209479177387814f;
        cin[1]  = -0.4886025119029199f * y;
        cin[2]  = 0.4886025119029199f * zc;
        cin[3]  = -0.4886025119029199f * x;
        cin[4]  = 1.0925484305920792f * xy;
        cin[5]  = -1.0925484305920792f * yz;
        cin[6]  = 0.31539156525252005f * (2.0f * zz - xx - yy);
        cin[7]  = -1.0925484305920792f * xz;
        cin[8]  = 0.5462742152960396f * (xx - yy);
        cin[9]  = -0.5900435899266435f * y * (3.0f * xx - yy);
        cin[10] = 2.890611442640554f * xy * zc;
        cin[11] = -0.4570457994644658f * y * (4.0f * zz - xx - yy);
        cin[12] = 0.3731763325901154f * zc * (2.0f * zz - 3.0f * xx - 3.0f * yy);
        cin[13] = -0.4570457994644658f * x * (4.0f * zz - xx - yy);
        cin[14] = 1.445305721320277f * zc * (xx - yy);
        cin[15] = -0.5900435899266435f * x * (xx - 3.0f * yy);
        #pragma unroll
        for (int j = 0; j < 15; j++) cin[16 + j] = h3[1 + j];
    }

    // ---- color MLP: 31 -> 64 -> 64 -> 64 -> 3 ----
    layer64(SW + SOFF_WC0, 31, cin, actl, true);
    {
        float tmp[64];
        layer64(c_W + COFF_WC1, 64, actl, tmp, true);
        layer64(c_W + COFF_WC2, 64, tmp, actl, true);
    }
    float col0 = 0.0f, col1 = 0.0f, col2 = 0.0f;
    #pragma unroll 1
    for (int i = 0; i < 64; i++) {
        const float v = actl[i];
        const float* wr = SW + SOFF_WC3 + i * 3;
        col0 = fmaf(v, wr[0], col0);
        col1 = fmaf(v, wr[1], col1);
        col2 = fmaf(v, wr[2], col2);
    }

    // ---- compositing (bit-identical alpha lattice) ----
    if (!keep) sigma = 0.0f;
    const float n2   = __fadd_rn(__fadd_rn(__fmul_rn(dx, dx), __fmul_rn(dy, dy)),
                                 __fmul_rn(dz, dz));
    const float norm = __fsqrt_rn(n2);
    const float dz_s = __fsub_rn(znext, z);
    const float dist = (s == 127) ? __fmul_rn(1e10f, norm) : __fmul_rn(dz_s, norm);
    const float xarg = __fmul_rn(fmaxf(sigma, 0.0f), dist);
    const float alpha = __fsub_rn(1.0f, exp32neg(xarg));

    s_alpha[s] = alpha;
    __syncthreads();
    if (s == 0) {
        float t = 1.0f;
        #pragma unroll 1
        for (int i = 0; i < 128; i++) {
            float a = s_alpha[i];
            s_w[i] = __fmul_rn(a, t);
            t = __fmul_rn(t, __fadd_rn(__fsub_rn(1.0f, a), 1e-10f));
        }
    }
    __syncthreads();
    const float wgt = s_w[s];

    const float sc0 = 1.0f / (1.0f + __nv_expf(-col0));
    const float sc1 = 1.0f / (1.0f + __nv_expf(-col1));
    const float sc2 = 1.0f / (1.0f + __nv_expf(-col2));

    float vals[5];
    vals[0] = wgt * sc0; vals[1] = wgt * sc1; vals[2] = wgt * sc2;
    vals[3] = wgt * z;   vals[4] = wgt;
    float res[5];
    #pragma unroll 1
    for (int t = 0; t < 5; t++) {
        float v = vals[t];
        #pragma unroll
        for (int o = 16; o > 0; o >>= 1) v += __shfl_down_sync(0xffffffffu, v, o);
        __syncthreads();
        if ((s & 31) == 0) s_red[s >> 5] = v;
        __syncthreads();
        res[t] = (s_red[0] + s_red[1]) + (s_red[2] + s_red[3]);
    }
    const float sw = res[4];

    const float plast = __fadd_rn(__fsub_rn(1.0f, sw), 1e-6f);
    const float S = __fadd_rn(sw, plast);
    float p = wgt / S;
    float ent = -p * __nv_logf(fmaxf(p, 1e-37f));
    if (s == 0) {
        float pl = plast / S;
        ent += -pl * __nv_logf(fmaxf(pl, 1e-37f));
    }
    {
        float v = ent;
        #pragma unroll
        for (int o = 16; o > 0; o >>= 1) v += __shfl_down_sync(0xffffffffu, v, o);
        __syncthreads();
        if ((s & 31) == 0) s_red[s >> 5] = v;
        __syncthreads();
        if (s == 0) {
            float rent = (s_red[0] + s_red[1]) + (s_red[2] + s_red[3]);
            out[ray * 3 + 0] = res[0];
            out[ray * 3 + 1] = res[1];
            out[ray * 3 + 2] = res[2];
            out[NRAYS * 3 + ray] = res[3];
            out[NRAYS * 4 + ray] = rent;
        }
    }
}

extern "C" void kernel_launch(void* const* d_in, const int* in_sizes, int n_in,
                              void* d_out, int out_size) {
    const float* rays   = (const float*)d_in[0];
    const float* tables = (const float*)d_in[1];
    const float* ws0    = (const float*)d_in[2];
    const float* ws1    = (const float*)d_in[3];
    const float* ws2    = (const float*)d_in[4];
    const float* wc0    = (const float*)d_in[5];
    const float* wc1    = (const float*)d_in[6];
    const float* wc2    = (const float*)d_in[7];
    const float* wc3    = (const float*)d_in[8];
    float* out = (float*)d_out;

    // Copy big weight matrices into constant memory (D2D async — graph-capturable)
    cudaMemcpyToSymbolAsync(c_W, ws0, 2048 * 4, COFF_WS0 * 4, cudaMemcpyDeviceToDevice, 0);
    cudaMemcpyToSymbolAsync(c_W, ws1, 4096 * 4, COFF_WS1 * 4, cudaMemcpyDeviceToDevice, 0);
    cudaMemcpyToSymbolAsync(c_W, wc1, 4096 * 4, COFF_WC1 * 4, cudaMemcpyDeviceToDevice, 0);
    cudaMemcpyToSymbolAsync(c_W, wc2, 4096 * 4, COFF_WC2 * 4, cudaMemcpyDeviceToDevice, 0);

    cudaFuncSetAttribute(nerf_fused, cudaFuncAttributeMaxDynamicSharedMemorySize, SMEM_BYTES);
    nerf_fused<<<NRAYS / RPB, NTHR, SMEM_BYTES>>>(rays, tables, ws2, wc0, wc3, out);
}

// round 14
// speedup vs baseline: 1.9940x; 1.9940x over previous
#include <cuda_runtime.h>
#include <math.h>

#define NRAYS   16384
#define TMASK   ((1u << 19) - 1u)
#define RPB     8                 // rays per block
#define NTHR    512               // 64 threads per ray, 2 samples per thread

extern "C" {
__device__ float  __nv_expf(float);
__device__ float  __nv_logf(float);
__device__ double __nv_exp(double);
}

// shared-memory weight offsets (in floats)
#define OFF_WS0 0        // 32x64
#define OFF_WS1 2048     // 64x64
#define OFF_WS2 6144     // 64x16
#define OFF_WC0 7168     // 31x64
#define OFF_WC1 9152     // 64x64
#define OFF_WC2 13248    // 64x64
#define OFF_WC3 17344    // 64x3
#define WTOT    17536

// per-ray smem: alpha[128] w[128] red[8] part[64]  (part 16B-aligned)
#define RAYBUF  328
#define SMEM_FLOATS (WTOT + RPB * RAYBUF)
#define SMEM_BYTES  (SMEM_FLOATS * 4)

__constant__ float c_res[16] = {16.f, 20.f, 25.f, 32.f, 40.f, 50.f, 64.f, 80.f,
                                101.f, 128.f, 161.f, 203.f, 256.f, 322.f, 406.f, 512.f};

typedef unsigned long long u64;

__device__ __forceinline__ u64 ffma2(u64 a, u64 b, u64 c) {
    u64 d;
    asm("fma.rn.f32x2 %0, %1, %2, %3;" : "=l"(d) : "l"(a), "l"(b), "l"(c));
    return d;
}
__device__ __forceinline__ u64 pack2(float v) {
    u64 d; unsigned r = __float_as_uint(v);
    asm("mov.b64 %0, {%1, %2};" : "=l"(d) : "r"(r), "r"(r));
    return d;
}
__device__ __forceinline__ void unpack2(u64 p, float& lo, float& hi) {
    asm("mov.b64 {%0, %1}, %2;" : "=f"(lo), "=f"(hi) : "l"(p));
}

// fl32(exp(-x)) for x >= 0, matching correctly-rounded fp32 exp bins.
__device__ __forceinline__ float exp32neg(float x) {
    if (x < 0.00048828125f) {               // 2^-11: poly path (~all samples)
        float t = __fmul_rn(x, x);
        float c = __fmaf_rn(x, -0.16666667f, 0.5f);   // 0.5 - x/6
        float y = __fmaf_rn(t, c, -x);                // -x + x^2/2 - x^3/6
        return __fadd_rn(1.0f, y);
    }
    if (x > 104.0f) return 0.0f;            // exp underflows past subnormals
    return (float)__nv_exp(-(double)x);     // rare middle band: exact fp64
}

// 64-output layer, two samples, quarter passes (bit-identical accumulation order).
__device__ __forceinline__ void layer64x2(const float* __restrict__ Wb, int n_in,
                                          const float* __restrict__ inA,
                                          const float* __restrict__ inB,
                                          float* __restrict__ outA,
                                          float* __restrict__ outB,
                                          const float* __restrict__ init) {
    #pragma unroll 1
    for (int q = 0; q < 4; q++) {
        u64 aA[8], aB[8];
        if (init) {
            const ulonglong2* ip = reinterpret_cast<const ulonglong2*>(init + q * 16);
            ulonglong2 i0 = ip[0], i1 = ip[1], i2 = ip[2], i3 = ip[3];
            aA[0]=i0.x; aA[1]=i0.y; aA[2]=i1.x; aA[3]=i1.y;
            aA[4]=i2.x; aA[5]=i2.y; aA[6]=i3.x; aA[7]=i3.y;
            #pragma unroll
            for (int k = 0; k < 8; k++) aB[k] = aA[k];
        } else {
            #pragma unroll
            for (int k = 0; k < 8; k++) { aA[k] = 0ULL; aB[k] = 0ULL; }
        }
        #pragma unroll 1
        for (int i = 0; i < n_in; i++) {
            const u64 vA = pack2(inA[i]);
            const u64 vB = pack2(inB[i]);
            const ulonglong2* wr = reinterpret_cast<const ulonglong2*>(Wb + i * 64 + q * 16);
            ulonglong2 w0 = wr[0], w1 = wr[1], w2 = wr[2], w3 = wr[3];
            aA[0]=ffma2(vA,w0.x,aA[0]); aB[0]=ffma2(vB,w0.x,aB[0]);
            aA[1]=ffma2(vA,w0.y,aA[1]); aB[1]=ffma2(vB,w0.y,aB[1]);
            aA[2]=ffma2(vA,w1.x,aA[2]); aB[2]=ffma2(vB,w1.x,aB[2]);
            aA[3]=ffma2(vA,w1.y,aA[3]); aB[3]=ffma2(vB,w1.y,aB[3]);
            aA[4]=ffma2(vA,w2.x,aA[4]); aB[4]=ffma2(vB,w2.x,aB[4]);
            aA[5]=ffma2(vA,w2.y,aA[5]); aB[5]=ffma2(vB,w2.y,aB[5]);
            aA[6]=ffma2(vA,w3.x,aA[6]); aB[6]=ffma2(vB,w3.x,aB[6]);
            aA[7]=ffma2(vA,w3.y,aA[7]); aB[7]=ffma2(vB,w3.y,aB[7]);
        }
        #pragma unroll
        for (int k = 0; k < 8; k++) {
            float lo, hi;
            unpack2(aA[k], lo, hi);
            outA[q*16 + 2*k]   = fmaxf(lo, 0.0f);
            outA[q*16 + 2*k+1] = fmaxf(hi, 0.0f);
            unpack2(aB[k], lo, hi);
            outB[q*16 + 2*k]   = fmaxf(lo, 0.0f);
            outB[q*16 + 2*k+1] = fmaxf(hi, 0.0f);
        }
    }
}

// 64 -> 16 layer (no relu), two samples.
__device__ __forceinline__ void layer16x2(const float* __restrict__ Wb,
                                          const float* __restrict__ inA,
                                          const float* __restrict__ inB,
                                          float* __restrict__ outA,
                                          float* __restrict__ outB) {
    u64 aA[8], aB[8];
    #pragma unroll
    for (int k = 0; k < 8; k++) { aA[k] = 0ULL; aB[k] = 0ULL; }
    #pragma unroll 1
    for (int i = 0; i < 64; i++) {
        const u64 vA = pack2(inA[i]);
        const u64 vB = pack2(inB[i]);
        const ulonglong2* wr = reinterpret_cast<const ulonglong2*>(Wb + i * 16);
        ulonglong2 w0 = wr[0], w1 = wr[1], w2 = wr[2], w3 = wr[3];
        aA[0]=ffma2(vA,w0.x,aA[0]); aB[0]=ffma2(vB,w0.x,aB[0]);
        aA[1]=ffma2(vA,w0.y,aA[1]); aB[1]=ffma2(vB,w0.y,aB[1]);
        aA[2]=ffma2(vA,w1.x,aA[2]); aB[2]=ffma2(vB,w1.x,aB[2]);
        aA[3]=ffma2(vA,w1.y,aA[3]); aB[3]=ffma2(vB,w1.y,aB[3]);
        aA[4]=ffma2(vA,w2.x,aA[4]); aB[4]=ffma2(vB,w2.x,aB[4]);
        aA[5]=ffma2(vA,w2.y,aA[5]); aB[5]=ffma2(vB,w2.y,aB[5]);
        aA[6]=ffma2(vA,w3.x,aA[6]); aB[6]=ffma2(vB,w3.x,aB[6]);
        aA[7]=ffma2(vA,w3.y,aA[7]); aB[7]=ffma2(vB,w3.y,aB[7]);
    }
    #pragma unroll
    for (int k = 0; k < 8; k++) {
        unpack2(aA[k], outA[2*k], outA[2*k+1]);
        unpack2(aB[k], outB[2*k], outB[2*k+1]);
    }
}

__device__ __forceinline__ void hash_encode(float cx, float cy, float cz,
                                            const float* __restrict__ tables,
                                            float* __restrict__ feat) {
    #pragma unroll 1
    for (int l = 0; l < 16; l++) {
        const float res  = c_res[l];
        const float grid = 3.0f / res;

        float tx = (cx - (-1.5f)) / grid;
        float ty = (cy - (-1.5f)) / grid;
        float tz = (cz - (-1.5f)) / grid;
        float fbx = floorf(tx), fby = floorf(ty), fbz = floorf(tz);
        float vmx = fbx * grid + (-1.5f);
        float vmy = fby * grid + (-1.5f);
        float vmz = fbz * grid + (-1.5f);
        float wx = (cx - vmx) / grid;
        float wy = (cy - vmy) / grid;
        float wz = (cz - vmz) / grid;

        unsigned bx = (unsigned)(int)fbx;
        unsigned by = (unsigned)(int)fby;
        unsigned bz = (unsigned)(int)fbz;

        unsigned hx0 = bx, hx1 = bx + 1u;
        unsigned hy0 = by * 2654435761u, hy1 = (by + 1u) * 2654435761u;
        unsigned hz0 = bz * 805459861u,  hz1 = (bz + 1u) * 805459861u;

        const float2* tab = reinterpret_cast<const float2*>(tables) + ((size_t)l << 19);
        float2 e000 = __ldg(&tab[(hx0 ^ hy0 ^ hz0) & TMASK]);
        float2 e001 = __ldg(&tab[(hx0 ^ hy0 ^ hz1) & TMASK]);
        float2 e010 = __ldg(&tab[(hx0 ^ hy1 ^ hz0) & TMASK]);
        float2 e011 = __ldg(&tab[(hx0 ^ hy1 ^ hz1) & TMASK]);
        float2 e100 = __ldg(&tab[(hx1 ^ hy0 ^ hz0) & TMASK]);
        float2 e101 = __ldg(&tab[(hx1 ^ hy0 ^ hz1) & TMASK]);
        float2 e110 = __ldg(&tab[(hx1 ^ hy1 ^ hz0) & TMASK]);
        float2 e111 = __ldg(&tab[(hx1 ^ hy1 ^ hz1) & TMASK]);

        const float u0 = 1.0f - wx, u1 = 1.0f - wy, u2 = 1.0f - wz;
        float c00a = e000.x * u0 + e100.x * wx, c00b = e000.y * u0 + e100.y * wx;
        float c01a = e001.x * u0 + e101.x * wx, c01b = e001.y * u0 + e101.y * wx;
        float c10a = e010.x * u0 + e110.x * wx, c10b = e010.y * u0 + e110.y * wx;
        float c11a = e011.x * u0 + e111.x * wx, c11b = e011.y * u0 + e111.y * wx;
        float c0a = c00a * u1 + c10a * wy, c0b = c00b * u1 + c10b * wy;
        float c1a = c01a * u1 + c11a * wy, c1b = c01b * u1 + c11b * wy;
        feat[l * 2 + 0] = c0a * u2 + c1a * wz;
        feat[l * 2 + 1] = c0b * u2 + c1b * wz;
    }
}

__global__ void __launch_bounds__(NTHR, 2)
nerf_fused(const float* __restrict__ rays,
           const float* __restrict__ tables,
           const float* __restrict__ ws0, const float* __restrict__ ws1,
           const float* __restrict__ ws2,
           const float* __restrict__ wc0, const float* __restrict__ wc1,
           const float* __restrict__ wc2, const float* __restrict__ wc3,
           float* __restrict__ out)
{
    extern __shared__ float sm[];
    float* W = sm;

    const int tid = threadIdx.x;
    const int r   = tid >> 6;          // ray slot (0..7)
    const int s0  = tid & 63;          // sample A
    const int s1  = s0 + 64;           // sample B
    const int ray = blockIdx.x * RPB + r;

    float* rb      = sm + WTOT + r * RAYBUF;
    float* s_alpha = rb;               // 128
    float* s_w     = rb + 128;         // 128
    float* s_red   = rb + 256;         // 8
    float* s_part  = rb + 264;         // 64 (16B-aligned)

    // ---- stage all MLP weights ----
    for (int i = tid; i < 2048; i += NTHR) W[OFF_WS0 + i] = ws0[i];
    for (int i = tid; i < 4096; i += NTHR) W[OFF_WS1 + i] = ws1[i];
    for (int i = tid; i < 1024; i += NTHR) W[OFF_WS2 + i] = ws2[i];
    for (int i = tid; i < 1984; i += NTHR) W[OFF_WC0 + i] = wc0[i];
    for (int i = tid; i < 4096; i += NTHR) W[OFF_WC1 + i] = wc1[i];
    for (int i = tid; i < 4096; i += NTHR) W[OFF_WC2 + i] = wc2[i];
    for (int i = tid; i < 192;  i += NTHR) W[OFF_WC3 + i] = wc3[i];
    __syncthreads();

    // ---- ray data ----
    const float ox = rays[ray * 6 + 0];
    const float oy = rays[ray * 6 + 1];
    const float oz = rays[ray * 6 + 2];
    const float dx = rays[ray * 6 + 3];
    const float dy = rays[ray * 6 + 4];
    const float dz = rays[ray * 6 + 5];

    // ---- SH(d): ray-constant; precompute wc0 partial (rows 0..15) ----
    {
        float sh[16];
        const float x = dx, y = dy, zc = dz;
        const float xx = x * x, yy = y * y, zz = zc * zc;
        const float xy = x * y, yz = y * zc, xz = x * zc;
        sh[0]  = 0.28209479177387814f;
        sh[1]  = -0.4886025119029199f * y;
        sh[2]  = 0.4886025119029199f * zc;
        sh[3]  = -0.4886025119029199f * x;
        sh[4]  = 1.0925484305920792f * xy;
        sh[5]  = -1.0925484305920792f * yz;
        sh[6]  = 0.31539156525252005f * (2.0f * zz - xx - yy);
        sh[7]  = -1.0925484305920792f * xz;
        sh[8]  = 0.5462742152960396f * (xx - yy);
        sh[9]  = -0.5900435899266435f * y * (3.0f * xx - yy);
        sh[10] = 2.890611442640554f * xy * zc;
        sh[11] = -0.4570457994644658f * y * (4.0f * zz - xx - yy);
        sh[12] = 0.3731763325901154f * zc * (2.0f * zz - 3.0f * xx - 3.0f * yy);
        sh[13] = -0.4570457994644658f * x * (4.0f * zz - xx - yy);
        sh[14] = 1.445305721320277f * zc * (xx - yy);
        sh[15] = -0.5900435899266435f * x * (xx - 3.0f * yy);
        float a = 0.0f;
        #pragma unroll
        for (int i = 0; i < 16; i++) a = fmaf(sh[i], W[OFF_WC0 + i * 64 + s0], a);
        s_part[s0] = a;
    }
    __syncthreads();

    // ---- per-sample positions ----
    const float step = 4.0f / 127.0f;
    const float zA  = __fadd_rn(2.0f, __fmul_rn(step, (float)s0));
    const float zAn = __fadd_rn(2.0f, __fmul_rn(step, (float)(s0 + 1)));
    const float zB  = __fadd_rn(2.0f, __fmul_rn(step, (float)s1));
    const float zBn = __fadd_rn(2.0f, __fmul_rn(step, (float)(s1 + 1)));

    float pxA = __fadd_rn(ox, __fmul_rn(dx, zA));
    float pyA = __fadd_rn(oy, __fmul_rn(dy, zA));
    float pzA = __fadd_rn(oz, __fmul_rn(dz, zA));
    float pxB = __fadd_rn(ox, __fmul_rn(dx, zB));
    float pyB = __fadd_rn(oy, __fmul_rn(dy, zB));
    float pzB = __fadd_rn(oz, __fmul_rn(dz, zB));

    const float cxA = fminf(fmaxf(pxA, -1.5f), 1.5f);
    const float cyA = fminf(fmaxf(pyA, -1.5f), 1.5f);
    const float czA = fminf(fmaxf(pzA, -1.5f), 1.5f);
    const bool keepA = (pxA == cxA) && (pyA == cyA) && (pzA == czA);
    const float cxB = fminf(fmaxf(pxB, -1.5f), 1.5f);
    const float cyB = fminf(fmaxf(pyB, -1.5f), 1.5f);
    const float czB = fminf(fmaxf(pzB, -1.5f), 1.5f);
    const bool keepB = (pxB == cxB) && (pyB == cyB) && (pzB == czB);

    // ---- hash encode both samples ----
    float featA[32], featB[32];
    hash_encode(cxA, cyA, czA, tables, featA);
    hash_encode(cxB, cyB, czB, tables, featB);

    // ---- sigma MLP ----
    float hA[64], hB[64], tA[64], tB[64];
    layer64x2(W + OFF_WS0, 32, featA, featB, hA, hB, 0);
    layer64x2(W + OFF_WS1, 64, hA, hB, tA, tB, 0);
    float h3A[16], h3B[16];
    layer16x2(W + OFF_WS2, tA, tB, h3A, h3B);
    float sigmaA = h3A[0], sigmaB = h3B[0];

    // ---- color MLP (wc0: init from SH partial, rows 16..30 are geo) ----
    layer64x2(W + OFF_WC0 + 16 * 64, 15, h3A + 1, h3B + 1, hA, hB, s_part);
    layer64x2(W + OFF_WC1, 64, hA, hB, tA, tB, 0);
    layer64x2(W + OFF_WC2, 64, tA, tB, hA, hB, 0);

    float c0A = 0.f, c1A = 0.f, c2A = 0.f, c0B = 0.f, c1B = 0.f, c2B = 0.f;
    #pragma unroll 1
    for (int i = 0; i < 64; i++) {
        const float* wr = W + OFF_WC3 + i * 3;
        float w0 = wr[0], w1 = wr[1], w2 = wr[2];
        c0A = fmaf(hA[i], w0, c0A); c0B = fmaf(hB[i], w0, c0B);
        c1A = fmaf(hA[i], w1, c1A); c1B = fmaf(hB[i], w1, c1B);
        c2A = fmaf(hA[i], w2, c2A); c2B = fmaf(hB[i], w2, c2B);
    }

    // ---- compositing (bit-identical alpha lattice) ----
    if (!keepA) sigmaA = 0.0f;
    if (!keepB) sigmaB = 0.0f;
    const float n2   = __fadd_rn(__fadd_rn(__fmul_rn(dx, dx), __fmul_rn(dy, dy)),
                                 __fmul_rn(dz, dz));
    const float norm = __fsqrt_rn(n2);
    const float distA = __fmul_rn(__fsub_rn(zAn, zA), norm);
    const float distB = (s1 == 127) ? __fmul_rn(1e10f, norm)
                                    : __fmul_rn(__fsub_rn(zBn, zB), norm);
    const float xA = __fmul_rn(fmaxf(sigmaA, 0.0f), distA);
    const float xB = __fmul_rn(fmaxf(sigmaB, 0.0f), distB);
    const float alphaA = __fsub_rn(1.0f, exp32neg(xA));
    const float alphaB = __fsub_rn(1.0f, exp32neg(xB));

    s_alpha[s0] = alphaA;
    s_alpha[s1] = alphaB;
    __syncthreads();
    if (s0 == 0) {
        float t = 1.0f;
        #pragma unroll 1
        for (int i = 0; i < 128; i++) {
            float a = s_alpha[i];
            s_w[i] = __fmul_rn(a, t);
            t = __fmul_rn(t, __fadd_rn(__fsub_rn(1.0f, a), 1e-10f));
        }
    }
    __syncthreads();
    const float wA = s_w[s0];
    const float wB = s_w[s1];

    const float scA0 = 1.0f / (1.0f + __nv_expf(-c0A));
    const float scA1 = 1.0f / (1.0f + __nv_expf(-c1A));
    const float scA2 = 1.0f / (1.0f + __nv_expf(-c2A));
    const float scB0 = 1.0f / (1.0f + __nv_expf(-c0B));
    const float scB1 = 1.0f / (1.0f + __nv_expf(-c1B));
    const float scB2 = 1.0f / (1.0f + __nv_expf(-c2B));

    float vals[5];
    vals[0] = wA * scA0 + wB * scB0;
    vals[1] = wA * scA1 + wB * scB1;
    vals[2] = wA * scA2 + wB * scB2;
    vals[3] = wA * zA   + wB * zB;
    vals[4] = wA + wB;
    float res[5];
    #pragma unroll 1
    for (int t = 0; t < 5; t++) {
        float v = vals[t];
        #pragma unroll
        for (int o = 16; o > 0; o >>= 1) v += __shfl_down_sync(0xffffffffu, v, o);
        __syncthreads();
        if ((tid & 31) == 0) s_red[(tid >> 5) & 1] = v;
        __syncthreads();
        res[t] = s_red[0] + s_red[1];
    }
    const float sw = res[4];

    const float plast = __fadd_rn(__fsub_rn(1.0f, sw), 1e-6f);
    const float S = __fadd_rn(sw, plast);
    float pA = wA / S, pB = wB / S;
    float ent = -pA * __nv_logf(fmaxf(pA, 1e-37f))
              + -pB * __nv_logf(fmaxf(pB, 1e-37f));
    if (s0 == 0) {
        float pl = plast / S;
        ent += -pl * __nv_logf(fmaxf(pl, 1e-37f));
    }
    {
        float v = ent;
        #pragma unroll
        for (int o = 16; o > 0; o >>= 1) v += __shfl_down_sync(0xffffffffu, v, o);
        __syncthreads();
        if ((tid & 31) == 0) s_red[(tid >> 5) & 1] = v;
        __syncthreads();
        if (s0 == 0) {
            float rent = s_red[0] + s_red[1];
            out[ray * 3 + 0] = res[0];
            out[ray * 3 + 1] = res[1];
            out[ray * 3 + 2] = res[2];
            out[NRAYS * 3 + ray] = res[3];
            out[NRAYS * 4 + ray] = rent;
        }
    }
}

extern "C" void kernel_launch(void* const* d_in, const int* in_sizes, int n_in,
                              void* d_out, int out_size) {
    const float* rays   = (const float*)d_in[0];
    const float* tables = (const float*)d_in[1];
    const float* ws0    = (const float*)d_in[2];
    const float* ws1    = (const float*)d_in[3];
    const float* ws2    = (const float*)d_in[4];
    const float* wc0    = (const float*)d_in[5];
    const float* wc1    = (const float*)d_in[6];
    const float* wc2    = (const float*)d_in[7];
    const float* wc3    = (const float*)d_in[8];
    float* out = (float*)d_out;

    cudaFuncSetAttribute(nerf_fused, cudaFuncAttributeMaxDynamicSharedMemorySize, SMEM_BYTES);
    nerf_fused<<<NRAYS / RPB, NTHR, SMEM_BYTES>>>(rays, tables, ws0, ws1, ws2,
                                                  wc0, wc1, wc2, wc3, out);
}

// round 15
// speedup vs baseline: 2.3340x; 1.1705x over previous
#include <cuda_runtime.h>
#include <math.h>

#define NRAYS   16384
#define NSAMP   128
#define TMASK   ((1u << 19) - 1u)
#define RPB     4                 // rays per block
#define NTHR    (128 * RPB)

extern "C" {
__device__ float  __nv_expf(float);
__device__ float  __nv_logf(float);
__device__ double __nv_exp(double);
}

// shared-memory weight offsets (in floats)
#define OFF_WS0 0        // 32x64
#define OFF_WS1 2048     // 64x64
#define OFF_WS2 6144     // 64x16
#define OFF_WC0 7168     // 31x64
#define OFF_WC1 9152     // 64x64
#define OFF_WC2 13248    // 64x64
#define OFF_WC3 17344    // 64x4 (padded from 64x3 for LDS.128)
#define WTOT    17600

#define RAYBUF  288               // per-ray: alpha[128] w[128] red[32]
#define SMEM_FLOATS (WTOT + RPB * RAYBUF)
#define SMEM_BYTES  (SMEM_FLOATS * 4)

__constant__ float c_res[16] = {16.f, 20.f, 25.f, 32.f, 40.f, 50.f, 64.f, 80.f,
                                101.f, 128.f, 161.f, 203.f, 256.f, 322.f, 406.f, 512.f};

typedef unsigned long long u64;

__device__ __forceinline__ u64 ffma2(u64 a, u64 b, u64 c) {
    u64 d;
    asm("fma.rn.f32x2 %0, %1, %2, %3;" : "=l"(d) : "l"(a), "l"(b), "l"(c));
    return d;
}
__device__ __forceinline__ u64 pack2(float v) {
    u64 d; unsigned r = __float_as_uint(v);
    asm("mov.b64 %0, {%1, %2};" : "=l"(d) : "r"(r), "r"(r));
    return d;
}
__device__ __forceinline__ void unpack2(u64 p, float& lo, float& hi) {
    asm("mov.b64 {%0, %1}, %2;" : "=f"(lo), "=f"(hi) : "l"(p));
}

// fl32(exp(-x)) for x >= 0, matching correctly-rounded fp32 exp bins.
// Poly path: err(y) ~ x*2^-24 => bin-flip prob ~2x per sample (~1e-6). Safe.
__device__ __forceinline__ float exp32neg(float x) {
    if (x < 0.00048828125f) {               // 2^-11 (covers ~all samples)
        float t = __fmul_rn(x, x);
        float c = __fmaf_rn(x, -0.16666667f, 0.5f);   // 0.5 - x/6
        float y = __fmaf_rn(t, c, -x);                // -x + x^2/2 - x^3/6
        return __fadd_rn(1.0f, y);
    }
    if (x > 104.0f) return 0.0f;            // exp underflows to 0
    return (float)__nv_exp(-(double)x);     // rare middle band: exact fp64
}

// 64-output layer in two 32-output half-passes (acc = 16 x b64 = 32 regs).
// Bit-identical accumulation order per output vs scalar version.
__device__ __forceinline__ void layer64(const float* __restrict__ Wb, int n_in,
                                        const float* __restrict__ in,
                                        float* __restrict__ outv, bool relu) {
    #pragma unroll 1
    for (int h = 0; h < 2; h++) {
        u64 acc2[16];
        #pragma unroll
        for (int k = 0; k < 16; k++) acc2[k] = 0ULL;
        #pragma unroll 1
        for (int i = 0; i < n_in; i++) {
            const u64 vv = pack2(in[i]);
            const ulonglong2* wr = reinterpret_cast<const ulonglong2*>(Wb + i * 64 + h * 32);
            #pragma unroll
            for (int q = 0; q < 8; q++) {
                ulonglong2 w2 = wr[q];
                acc2[2*q]   = ffma2(vv, w2.x, acc2[2*q]);
                acc2[2*q+1] = ffma2(vv, w2.y, acc2[2*q+1]);
            }
        }
        #pragma unroll
        for (int k = 0; k < 16; k++) {
            float lo, hi;
            unpack2(acc2[k], lo, hi);
            if (relu) { lo = fmaxf(lo, 0.0f); hi = fmaxf(hi, 0.0f); }
            outv[h * 32 + 2*k]     = lo;
            outv[h * 32 + 2*k + 1] = hi;
        }
    }
}

__global__ void __launch_bounds__(NTHR, 2)
nerf_fused(const float* __restrict__ rays,
           const float* __restrict__ tables,
           const float* __restrict__ ws0, const float* __restrict__ ws1,
           const float* __restrict__ ws2,
           const float* __restrict__ wc0, const float* __restrict__ wc1,
           const float* __restrict__ wc2, const float* __restrict__ wc3,
           float* __restrict__ out)
{
    extern __shared__ float sm[];
    float* W = sm;

    const int tid = threadIdx.x;
    const int r   = tid >> 7;         // ray slot in block
    const int s   = tid & 127;        // sample index
    const int ray = blockIdx.x * RPB + r;

    float* rb      = sm + WTOT + r * RAYBUF;
    float* s_alpha = rb;              // 128
    float* s_w     = rb + 128;        // 128
    float* s_red   = rb + 256;        // 32 (24 used)

    // ---- stage all MLP weights (wc3 repacked to stride 4) ----
    for (int i = tid; i < 2048; i += NTHR) W[OFF_WS0 + i] = ws0[i];
    for (int i = tid; i < 4096; i += NTHR) W[OFF_WS1 + i] = ws1[i];
    for (int i = tid; i < 1024; i += NTHR) W[OFF_WS2 + i] = ws2[i];
    for (int i = tid; i < 1984; i += NTHR) W[OFF_WC0 + i] = wc0[i];
    for (int i = tid; i < 4096; i += NTHR) W[OFF_WC1 + i] = wc1[i];
    for (int i = tid; i < 4096; i += NTHR) W[OFF_WC2 + i] = wc2[i];
    for (int i = tid; i < 256;  i += NTHR) {
        int row = i >> 2, col = i & 3;
        W[OFF_WC3 + i] = (col < 3) ? wc3[row * 3 + col] : 0.0f;
    }
    __syncthreads();

    // ---- ray / sample setup ----
    const float ox = rays[ray * 6 + 0];
    const float oy = rays[ray * 6 + 1];
    const float oz = rays[ray * 6 + 2];
    const float dx = rays[ray * 6 + 3];
    const float dy = rays[ray * 6 + 4];
    const float dz = rays[ray * 6 + 5];

    const float step = 4.0f / 127.0f;
    const float z     = __fadd_rn(2.0f, __fmul_rn(step, (float)s));
    const float znext = __fadd_rn(2.0f, __fmul_rn(step, (float)(s + 1)));

    const float px = __fadd_rn(ox, __fmul_rn(dx, z));
    const float py = __fadd_rn(oy, __fmul_rn(dy, z));
    const float pz = __fadd_rn(oz, __fmul_rn(dz, z));

    const float cx = fminf(fmaxf(px, -1.5f), 1.5f);
    const float cy = fminf(fmaxf(py, -1.5f), 1.5f);
    const float cz = fminf(fmaxf(pz, -1.5f), 1.5f);
    const bool keep = (px == cx) && (py == cy) && (pz == cz);

    // ---- multi-resolution hash encoding ----
    float featl[32];
    #pragma unroll 1
    for (int l = 0; l < 16; l++) {
        const float res  = c_res[l];
        const float grid = 3.0f / res;

        float tx = (cx - (-1.5f)) / grid;
        float ty = (cy - (-1.5f)) / grid;
        float tz = (cz - (-1.5f)) / grid;
        float fbx = floorf(tx), fby = floorf(ty), fbz = floorf(tz);
        float vmx = fbx * grid + (-1.5f);
        float vmy = fby * grid + (-1.5f);
        float vmz = fbz * grid + (-1.5f);
        float wx = (cx - vmx) / grid;
        float wy = (cy - vmy) / grid;
        float wz = (cz - vmz) / grid;

        unsigned bx = (unsigned)(int)fbx;
        unsigned by = (unsigned)(int)fby;
        unsigned bz = (unsigned)(int)fbz;

        unsigned hx0 = bx, hx1 = bx + 1u;
        unsigned hy0 = by * 2654435761u, hy1 = (by + 1u) * 2654435761u;
        unsigned hz0 = bz * 805459861u,  hz1 = (bz + 1u) * 805459861u;

        const float2* tab = reinterpret_cast<const float2*>(tables) + ((size_t)l << 19);
        float2 e000 = __ldg(&tab[(hx0 ^ hy0 ^ hz0) & TMASK]);
        float2 e001 = __ldg(&tab[(hx0 ^ hy0 ^ hz1) & TMASK]);
        float2 e010 = __ldg(&tab[(hx0 ^ hy1 ^ hz0) & TMASK]);
        float2 e011 = __ldg(&tab[(hx0 ^ hy1 ^ hz1) & TMASK]);
        float2 e100 = __ldg(&tab[(hx1 ^ hy0 ^ hz0) & TMASK]);
        float2 e101 = __ldg(&tab[(hx1 ^ hy0 ^ hz1) & TMASK]);
        float2 e110 = __ldg(&tab[(hx1 ^ hy1 ^ hz0) & TMASK]);
        float2 e111 = __ldg(&tab[(hx1 ^ hy1 ^ hz1) & TMASK]);

        const float u0 = 1.0f - wx, u1 = 1.0f - wy, u2 = 1.0f - wz;
        float c00a = e000.x * u0 + e100.x * wx, c00b = e000.y * u0 + e100.y * wx;
        float c01a = e001.x * u0 + e101.x * wx, c01b = e001.y * u0 + e101.y * wx;
        float c10a = e010.x * u0 + e110.x * wx, c10b = e010.y * u0 + e110.y * wx;
        float c11a = e011.x * u0 + e111.x * wx, c11b = e011.y * u0 + e111.y * wx;
        float c0a = c00a * u1 + c10a * wy, c0b = c00b * u1 + c10b * wy;
        float c1a = c01a * u1 + c11a * wy, c1b = c01b * u1 + c11b * wy;
        featl[l * 2 + 0] = c0a * u2 + c1a * wz;
        featl[l * 2 + 1] = c0b * u2 + c1b * wz;
    }

    // ---- sigma MLP: 32 -> 64 -> 64 -> 16 ----
    float actl[64];
    layer64(W + OFF_WS0, 32, featl, actl, true);
    {
        float tmp[64];
        layer64(W + OFF_WS1, 64, actl, tmp, true);
        #pragma unroll
        for (int j = 0; j < 64; j++) actl[j] = tmp[j];
    }
    float h3[16];
    {   // 64 -> 16, single pass (acc = 8 x b64)
        u64 acc2[8];
        #pragma unroll
        for (int k = 0; k < 8; k++) acc2[k] = 0ULL;
        #pragma unroll 1
        for (int i = 0; i < 64; i++) {
            const u64 vv = pack2(actl[i]);
            const ulonglong2* wr = reinterpret_cast<const ulonglong2*>(W + OFF_WS2 + i * 16);
            #pragma unroll
            for (int q = 0; q < 4; q++) {
                ulonglong2 w2 = wr[q];
                acc2[2*q]   = ffma2(vv, w2.x, acc2[2*q]);
                acc2[2*q+1] = ffma2(vv, w2.y, acc2[2*q+1]);
            }
        }
        #pragma unroll
        for (int k = 0; k < 8; k++) unpack2(acc2[k], h3[2*k], h3[2*k+1]);
    }
    float sigma = h3[0];

    // ---- SH + geo -> color input (31) ----
    float cin[31];
    {
        const float x = dx, y = dy, zc = dz;
        const float xx = x * x, yy = y * y, zz = zc * zc;
        const float xy = x * y, yz = y * zc, xz = x * zc;
        cin[0]  = 0.28209479177387814f;
        cin[1]  = -0.4886025119029199f * y;
        cin[2]  = 0.4886025119029199f * zc;
        cin[3]  = -0.4886025119029199f * x;
        cin[4]  = 1.0925484305920792f * xy;
        cin[5]  = -1.0925484305920792f * yz;
        cin[6]  = 0.31539156525252005f * (2.0f * zz - xx - yy);
        cin[7]  = -1.0925484305920792f * xz;
        cin[8]  = 0.5462742152960396f * (xx - yy);
        cin[9]  = -0.5900435899266435f * y * (3.0f * xx - yy);
        cin[10] = 2.890611442640554f * xy * zc;
        cin[11] = -0.4570457994644658f * y * (4.0f * zz - xx - yy);
        cin[12] = 0.3731763325901154f * zc * (2.0f * zz - 3.0f * xx - 3.0f * yy);
        cin[13] = -0.4570457994644658f * x * (4.0f * zz - xx - yy);
        cin[14] = 1.445305721320277f * zc * (xx - yy);
        cin[15] = -0.5900435899266435f * x * (xx - 3.0f * yy);
        #pragma unroll
        for (int j = 0; j < 15; j++) cin[16 + j] = h3[1 + j];
    }

    // ---- color MLP: 31 -> 64 -> 64 -> 64 -> 3 ----
    layer64(W + OFF_WC0, 31, cin, actl, true);
    {
        float tmp[64];
        layer64(W + OFF_WC1, 64, actl, tmp, true);
        layer64(W + OFF_WC2, 64, tmp, actl, true);
    }
    float col0 = 0.0f, col1 = 0.0f, col2 = 0.0f;
    #pragma unroll 1
    for (int i = 0; i < 64; i++) {
        const float v = actl[i];
        const float4 w4 = *reinterpret_cast<const float4*>(W + OFF_WC3 + i * 4);
        col0 = fmaf(v, w4.x, col0);
        col1 = fmaf(v, w4.y, col1);
        col2 = fmaf(v, w4.z, col2);
    }

    // ---- compositing (bit-identical alpha lattice) ----
    if (!keep) sigma = 0.0f;
    const float n2   = __fadd_rn(__fadd_rn(__fmul_rn(dx, dx), __fmul_rn(dy, dy)),
                                 __fmul_rn(dz, dz));
    const float norm = __fsqrt_rn(n2);
    const float dz_s = __fsub_rn(znext, z);
    const float dist = (s == 127) ? __fmul_rn(1e10f, norm) : __fmul_rn(dz_s, norm);
    const float xarg = __fmul_rn(fmaxf(sigma, 0.0f), dist);
    const float alpha = __fsub_rn(1.0f, exp32neg(xarg));

    s_alpha[s] = alpha;
    __syncthreads();
    if (s == 0) {
        float t = 1.0f;
        #pragma unroll 1
        for (int i = 0; i < 128; i++) {
            float a = s_alpha[i];
            s_w[i] = __fmul_rn(a, t);
            t = __fmul_rn(t, __fadd_rn(__fsub_rn(1.0f, a), 1e-10f));
        }
    }
    __syncthreads();
    const float wgt = s_w[s];

    const float sc0 = 1.0f / (1.0f + __nv_expf(-col0));
    const float sc1 = 1.0f / (1.0f + __nv_expf(-col1));
    const float sc2 = 1.0f / (1.0f + __nv_expf(-col2));

    // ---- tail reductions: one shuffle pass for 5 values, 2 block syncs ----
    float v0 = wgt * sc0, v1 = wgt * sc1, v2 = wgt * sc2, v3 = wgt * z, v4 = wgt;
    #pragma unroll
    for (int o = 16; o > 0; o >>= 1) {
        v0 += __shfl_down_sync(0xffffffffu, v0, o);
        v1 += __shfl_down_sync(0xffffffffu, v1, o);
        v2 += __shfl_down_sync(0xffffffffu, v2, o);
        v3 += __shfl_down_sync(0xffffffffu, v3, o);
        v4 += __shfl_down_sync(0xffffffffu, v4, o);
    }
    if ((s & 31) == 0) {
        const int w = s >> 5;                  // warp slot 0..3
        s_red[w]      = v0;
        s_red[4 + w]  = v1;
        s_red[8 + w]  = v2;
        s_red[12 + w] = v3;
        s_red[16 + w] = v4;
    }
    __syncthreads();
    const float r0 = (s_red[0]  + s_red[1])  + (s_red[2]  + s_red[3]);
    const float r1 = (s_red[4]  + s_red[5])  + (s_red[6]  + s_red[7]);
    const float r2 = (s_red[8]  + s_red[9])  + (s_red[10] + s_red[11]);
    const float rd = (s_red[12] + s_red[13]) + (s_red[14] + s_red[15]);
    const float sw = (s_red[16] + s_red[17]) + (s_red[18] + s_red[19]);

    const float plast = __fadd_rn(__fsub_rn(1.0f, sw), 1e-6f);
    const float S = __fadd_rn(sw, plast);
    float p = wgt / S;
    float ent = -p * __nv_logf(fmaxf(p, 1e-37f));
    if (s == 0) {
        float pl = plast / S;
        ent += -pl * __nv_logf(fmaxf(pl, 1e-37f));
    }
    #pragma unroll
    for (int o = 16; o > 0; o >>= 1) ent += __shfl_down_sync(0xffffffffu, ent, o);
    if ((s & 31) == 0) s_red[20 + (s >> 5)] = ent;
    __syncthreads();
    if (s == 0) {
        const float rent = (s_red[20] + s_red[21]) + (s_red[22] + s_red[23]);
        out[ray * 3 + 0] = r0;
        out[ray * 3 + 1] = r1;
        out[ray * 3 + 2] = r2;
        out[NRAYS * 3 + ray] = rd;
        out[NRAYS * 4 + ray] = rent;
    }
}

extern "C" void kernel_launch(void* const* d_in, const int* in_sizes, int n_in,
                              void* d_out, int out_size) {
    const float* rays   = (const float*)d_in[0];
    const float* tables = (const float*)d_in[1];
    const float* ws0    = (const float*)d_in[2];
    const float* ws1    = (const float*)d_in[3];
    const float* ws2    = (const float*)d_in[4];
    const float* wc0    = (const float*)d_in[5];
    const float* wc1    = (const float*)d_in[6];
    const float* wc2    = (const float*)d_in[7];
    const float* wc3    = (const float*)d_in[8];
    float* out = (float*)d_out;

    cudaFuncSetAttribute(nerf_fused, cudaFuncAttributeMaxDynamicSharedMemorySize, SMEM_BYTES);
    nerf_fused<<<NRAYS / RPB, NTHR, SMEM_BYTES>>>(rays, tables, ws0, ws1, ws2,
                                                  wc0, wc1, wc2, wc3, out);
}

// round 16
// speedup vs baseline: 7.7735x; 3.3306x over previous
#include <cuda_runtime.h>
#include <math.h>

#define NRAYS   16384
#define NSAMP   128
#define TMASK   ((1u << 19) - 1u)
#define RPB     4                 // rays per block
#define NTHR    (128 * RPB)
#define NWARPS  (NTHR / 32)

extern "C" {
__device__ float  __nv_expf(float);
__device__ float  __nv_logf(float);
__device__ double __nv_exp(double);
}

// shared-memory weight offsets (in floats)
#define OFF_WS0 0        // 32x64
#define OFF_WS1 2048     // 64x64
#define OFF_WS2 6144     // 64x16
#define OFF_WC0 7168     // 31x64
#define OFF_WC1 9152     // 64x64
#define OFF_WC2 13248    // 64x64
#define OFF_WC3 17344    // 64x4 (padded from 64x3 for LDS.128)
#define WTOT    17600

#define RAYBUF  288               // per-ray: alpha[128] w[128] red[32]
#define SMEM_FLOATS (WTOT + RPB * RAYBUF + NWARPS)
#define SMEM_BYTES  (SMEM_FLOATS * 4)

__constant__ float c_res[16] = {16.f, 20.f, 25.f, 32.f, 40.f, 50.f, 64.f, 80.f,
                                101.f, 128.f, 161.f, 203.f, 256.f, 322.f, 406.f, 512.f};

typedef unsigned long long u64;

__device__ __forceinline__ u64 ffma2(u64 a, u64 b, u64 c) {
    u64 d;
    asm("fma.rn.f32x2 %0, %1, %2, %3;" : "=l"(d) : "l"(a), "l"(b), "l"(c));
    return d;
}
__device__ __forceinline__ u64 pack2(float v) {
    u64 d; unsigned r = __float_as_uint(v);
    asm("mov.b64 %0, {%1, %2};" : "=l"(d) : "r"(r), "r"(r));
    return d;
}
__device__ __forceinline__ void unpack2(u64 p, float& lo, float& hi) {
    asm("mov.b64 {%0, %1}, %2;" : "=f"(lo), "=f"(hi) : "l"(p));
}

// fl32(exp(-x)) for x >= 0, matching correctly-rounded fp32 exp bins.
__device__ __forceinline__ float exp32neg(float x) {
    if (x < 0.00048828125f) {               // 2^-11 (covers ~all samples)
        float t = __fmul_rn(x, x);
        float c = __fmaf_rn(x, -0.16666667f, 0.5f);   // 0.5 - x/6
        float y = __fmaf_rn(t, c, -x);                // -x + x^2/2 - x^3/6
        return __fadd_rn(1.0f, y);
    }
    if (x > 104.0f) return 0.0f;            // exp underflows to 0
    return (float)__nv_exp(-(double)x);     // rare middle band: exact fp64
}

// 64-output layer in two 32-output half-passes (acc = 16 x b64 = 32 regs).
__device__ __forceinline__ void layer64(const float* __restrict__ Wb, int n_in,
                                        const float* __restrict__ in,
                                        float* __restrict__ outv, bool relu) {
    #pragma unroll 1
    for (int h = 0; h < 2; h++) {
        u64 acc2[16];
        #pragma unroll
        for (int k = 0; k < 16; k++) acc2[k] = 0ULL;
        #pragma unroll 1
        for (int i = 0; i < n_in; i++) {
            const u64 vv = pack2(in[i]);
            const ulonglong2* wr = reinterpret_cast<const ulonglong2*>(Wb + i * 64 + h * 32);
            #pragma unroll
            for (int q = 0; q < 8; q++) {
                ulonglong2 w2 = wr[q];
                acc2[2*q]   = ffma2(vv, w2.x, acc2[2*q]);
                acc2[2*q+1] = ffma2(vv, w2.y, acc2[2*q+1]);
            }
        }
        #pragma unroll
        for (int k = 0; k < 16; k++) {
            float lo, hi;
            unpack2(acc2[k], lo, hi);
            if (relu) { lo = fmaxf(lo, 0.0f); hi = fmaxf(hi, 0.0f); }
            outv[h * 32 + 2*k]     = lo;
            outv[h * 32 + 2*k + 1] = hi;
        }
    }
}

__global__ void __launch_bounds__(NTHR, 2)
nerf_fused(const float* __restrict__ rays,
           const float* __restrict__ tables,
           const float* __restrict__ ws0, const float* __restrict__ ws1,
           const float* __restrict__ ws2,
           const float* __restrict__ wc0, const float* __restrict__ wc1,
           const float* __restrict__ wc2, const float* __restrict__ wc3,
           float* __restrict__ out)
{
    extern __shared__ float sm[];
    float* W = sm;

    const int tid = threadIdx.x;
    const int r   = tid >> 7;         // ray slot in block
    const int s   = tid & 127;        // sample index
    const int ray = blockIdx.x * RPB + r;

    float* rb      = sm + WTOT + r * RAYBUF;
    float* s_alpha = rb;              // 128
    float* s_w     = rb + 128;        // 128
    float* s_red   = rb + 256;        // 32 (24 used)
    int*   s_vote  = (int*)(sm + WTOT + RPB * RAYBUF);  // NWARPS ints

    // ---- ray / sample setup (cheap; done before any staging) ----
    const float ox = rays[ray * 6 + 0];
    const float oy = rays[ray * 6 + 1];
    const float oz = rays[ray * 6 + 2];
    const float dx = rays[ray * 6 + 3];
    const float dy = rays[ray * 6 + 4];
    const float dz = rays[ray * 6 + 5];

    const float step = 4.0f / 127.0f;
    const float z     = __fadd_rn(2.0f, __fmul_rn(step, (float)s));
    const float znext = __fadd_rn(2.0f, __fmul_rn(step, (float)(s + 1)));

    const float px = __fadd_rn(ox, __fmul_rn(dx, z));
    const float py = __fadd_rn(oy, __fmul_rn(dy, z));
    const float pz = __fadd_rn(oz, __fmul_rn(dz, z));

    const float cx = fminf(fmaxf(px, -1.5f), 1.5f);
    const float cy = fminf(fmaxf(py, -1.5f), 1.5f);
    const float cz = fminf(fmaxf(pz, -1.5f), 1.5f);
    const bool keep = (px == cx) && (py == cy) && (pz == cz);

    // ---- warp / block activity votes ----
    const bool warp_active = __any_sync(0xffffffffu, keep);
    if ((tid & 31) == 0) s_vote[tid >> 5] = warp_active ? 1 : 0;
    __syncthreads();
    bool block_active = false;
    #pragma unroll
    for (int w = 0; w < NWARPS; w++) block_active |= (s_vote[w] != 0);

    // ---- stage all MLP weights (only if some warp needs them) ----
    if (block_active) {
        for (int i = tid; i < 2048; i += NTHR) W[OFF_WS0 + i] = ws0[i];
        for (int i = tid; i < 4096; i += NTHR) W[OFF_WS1 + i] = ws1[i];
        for (int i = tid; i < 1024; i += NTHR) W[OFF_WS2 + i] = ws2[i];
        for (int i = tid; i < 1984; i += NTHR) W[OFF_WC0 + i] = wc0[i];
        for (int i = tid; i < 4096; i += NTHR) W[OFF_WC1 + i] = wc1[i];
        for (int i = tid; i < 4096; i += NTHR) W[OFF_WC2 + i] = wc2[i];
        for (int i = tid; i < 256;  i += NTHR) {
            int row = i >> 2, col = i & 3;
            W[OFF_WC3 + i] = (col < 3) ? wc3[row * 3 + col] : 0.0f;
        }
    }
    __syncthreads();

    float sigma = 0.0f, col0 = 0.0f, col1 = 0.0f, col2 = 0.0f;

    if (warp_active) {
        // ---- multi-resolution hash encoding ----
        float featl[32];
        #pragma unroll 1
        for (int l = 0; l < 16; l++) {
            const float res  = c_res[l];
            const float grid = 3.0f / res;

            float tx = (cx - (-1.5f)) / grid;
            float ty = (cy - (-1.5f)) / grid;
            float tz = (cz - (-1.5f)) / grid;
            float fbx = floorf(tx), fby = floorf(ty), fbz = floorf(tz);
            float vmx = fbx * grid + (-1.5f);
            float vmy = fby * grid + (-1.5f);
            float vmz = fbz * grid + (-1.5f);
            float wx = (cx - vmx) / grid;
            float wy = (cy - vmy) / grid;
            float wz = (cz - vmz) / grid;

            unsigned bx = (unsigned)(int)fbx;
            unsigned by = (unsigned)(int)fby;
            unsigned bz = (unsigned)(int)fbz;

            unsigned hx0 = bx, hx1 = bx + 1u;
            unsigned hy0 = by * 2654435761u, hy1 = (by + 1u) * 2654435761u;
            unsigned hz0 = bz * 805459861u,  hz1 = (bz + 1u) * 805459861u;

            const float2* tab = reinterpret_cast<const float2*>(tables) + ((size_t)l << 19);
            float2 e000 = __ldg(&tab[(hx0 ^ hy0 ^ hz0) & TMASK]);
            float2 e001 = __ldg(&tab[(hx0 ^ hy0 ^ hz1) & TMASK]);
            float2 e010 = __ldg(&tab[(hx0 ^ hy1 ^ hz0) & TMASK]);
            float2 e011 = __ldg(&tab[(hx0 ^ hy1 ^ hz1) & TMASK]);
            float2 e100 = __ldg(&tab[(hx1 ^ hy0 ^ hz0) & TMASK]);
            float2 e101 = __ldg(&tab[(hx1 ^ hy0 ^ hz1) & TMASK]);
            float2 e110 = __ldg(&tab[(hx1 ^ hy1 ^ hz0) & TMASK]);
            float2 e111 = __ldg(&tab[(hx1 ^ hy1 ^ hz1) & TMASK]);

            const float u0 = 1.0f - wx, u1 = 1.0f - wy, u2 = 1.0f - wz;
            float c00a = e000.x * u0 + e100.x * wx, c00b = e000.y * u0 + e100.y * wx;
            float c01a = e001.x * u0 + e101.x * wx, c01b = e001.y * u0 + e101.y * wx;
            float c10a = e010.x * u0 + e110.x * wx, c10b = e010.y * u0 + e110.y * wx;
            float c11a = e011.x * u0 + e111.x * wx, c11b = e011.y * u0 + e111.y * wx;
            float c0a = c00a * u1 + c10a * wy, c0b = c00b * u1 + c10b * wy;
            float c1a = c01a * u1 + c11a * wy, c1b = c01b * u1 + c11b * wy;
            featl[l * 2 + 0] = c0a * u2 + c1a * wz;
            featl[l * 2 + 1] = c0b * u2 + c1b * wz;
        }

        // ---- sigma MLP: 32 -> 64 -> 64 -> 16 ----
        float actl[64];
        layer64(W + OFF_WS0, 32, featl, actl, true);
        {
            float tmp[64];
            layer64(W + OFF_WS1, 64, actl, tmp, true);
            #pragma unroll
            for (int j = 0; j < 64; j++) actl[j] = tmp[j];
        }
        float h3[16];
        {
            u64 acc2[8];
            #pragma unroll
            for (int k = 0; k < 8; k++) acc2[k] = 0ULL;
            #pragma unroll 1
            for (int i = 0; i < 64; i++) {
                const u64 vv = pack2(actl[i]);
                const ulonglong2* wr = reinterpret_cast<const ulonglong2*>(W + OFF_WS2 + i * 16);
                #pragma unroll
                for (int q = 0; q < 4; q++) {
                    ulonglong2 w2 = wr[q];
                    acc2[2*q]   = ffma2(vv, w2.x, acc2[2*q]);
                    acc2[2*q+1] = ffma2(vv, w2.y, acc2[2*q+1]);
                }
            }
            #pragma unroll
            for (int k = 0; k < 8; k++) unpack2(acc2[k], h3[2*k], h3[2*k+1]);
        }
        sigma = h3[0];

        // ---- SH + geo -> color input (31) ----
        float cin[31];
        {
            const float x = dx, y = dy, zc = dz;
            const float xx = x * x, yy = y * y, zz = zc * zc;
            const float xy = x * y, yz = y * zc, xz = x * zc;
            cin[0]  = 0.28209479177387814f;
            cin[1]  = -0.4886025119029199f * y;
            cin[2]  = 0.4886025119029199f * zc;
            cin[3]  = -0.4886025119029199f * x;
            cin[4]  = 1.0925484305920792f * xy;
            cin[5]  = -1.0925484305920792f * yz;
            cin[6]  = 0.31539156525252005f * (2.0f * zz - xx - yy);
            cin[7]  = -1.0925484305920792f * xz;
            cin[8]  = 0.5462742152960396f * (xx - yy);
            cin[9]  = -0.5900435899266435f * y * (3.0f * xx - yy);
            cin[10] = 2.890611442640554f * xy * zc;
            cin[11] = -0.4570457994644658f * y * (4.0f * zz - xx - yy);
            cin[12] = 0.3731763325901154f * zc * (2.0f * zz - 3.0f * xx - 3.0f * yy);
            cin[13] = -0.4570457994644658f * x * (4.0f * zz - xx - yy);
            cin[14] = 1.445305721320277f * zc * (xx - yy);
            cin[15] = -0.5900435899266435f * x * (xx - 3.0f * yy);
            #pragma unroll
            for (int j = 0; j < 15; j++) cin[16 + j] = h3[1 + j];
        }

        // ---- color MLP: 31 -> 64 -> 64 -> 64 -> 3 ----
        layer64(W + OFF_WC0, 31, cin, actl, true);
        {
            float tmp[64];
            layer64(W + OFF_WC1, 64, actl, tmp, true);
            layer64(W + OFF_WC2, 64, tmp, actl, true);
        }
        #pragma unroll 1
        for (int i = 0; i < 64; i++) {
            const float v = actl[i];
            const float4 w4 = *reinterpret_cast<const float4*>(W + OFF_WC3 + i * 4);
            col0 = fmaf(v, w4.x, col0);
            col1 = fmaf(v, w4.y, col1);
            col2 = fmaf(v, w4.z, col2);
        }

        if (!keep) sigma = 0.0f;
    }

    // ---- compositing (bit-identical alpha lattice) ----
    const float n2   = __fadd_rn(__fadd_rn(__fmul_rn(dx, dx), __fmul_rn(dy, dy)),
                                 __fmul_rn(dz, dz));
    const float norm = __fsqrt_rn(n2);
    const float dz_s = __fsub_rn(znext, z);
    const float dist = (s == 127) ? __fmul_rn(1e10f, norm) : __fmul_rn(dz_s, norm);
    const float xarg = __fmul_rn(fmaxf(sigma, 0.0f), dist);
    const float alpha = __fsub_rn(1.0f, exp32neg(xarg));

    s_alpha[s] = alpha;
    __syncthreads();
    if (s == 0) {
        float t = 1.0f;
        #pragma unroll 1
        for (int i = 0; i < 128; i++) {
            float a = s_alpha[i];
            s_w[i] = __fmul_rn(a, t);
            t = __fmul_rn(t, __fadd_rn(__fsub_rn(1.0f, a), 1e-10f));
        }
    }
    __syncthreads();
    const float wgt = s_w[s];

    const float sc0 = 1.0f / (1.0f + __nv_expf(-col0));
    const float sc1 = 1.0f / (1.0f + __nv_expf(-col1));
    const float sc2 = 1.0f / (1.0f + __nv_expf(-col2));

    // ---- tail reductions ----
    float v0 = wgt * sc0, v1 = wgt * sc1, v2 = wgt * sc2, v3 = wgt * z, v4 = wgt;
    #pragma unroll
    for (int o = 16; o > 0; o >>= 1) {
        v0 += __shfl_down_sync(0xffffffffu, v0, o);
        v1 += __shfl_down_sync(0xffffffffu, v1, o);
        v2 += __shfl_down_sync(0xffffffffu, v2, o);
        v3 += __shfl_down_sync(0xffffffffu, v3, o);
        v4 += __shfl_down_sync(0xffffffffu, v4, o);
    }
    if ((s & 31) == 0) {
        const int w = s >> 5;
        s_red[w]      = v0;
        s_red[4 + w]  = v1;
        s_red[8 + w]  = v2;
        s_red[12 + w] = v3;
        s_red[16 + w] = v4;
    }
    __syncthreads();
    const float r0 = (s_red[0]  + s_red[1])  + (s_red[2]  + s_red[3]);
    const float r1 = (s_red[4]  + s_red[5])  + (s_red[6]  + s_red[7]);
    const float r2 = (s_red[8]  + s_red[9])  + (s_red[10] + s_red[11]);
    const float rd = (s_red[12] + s_red[13]) + (s_red[14] + s_red[15]);
    const float sw = (s_red[16] + s_red[17]) + (s_red[18] + s_red[19]);

    const float plast = __fadd_rn(__fsub_rn(1.0f, sw), 1e-6f);
    const float S = __fadd_rn(sw, plast);
    float p = wgt / S;
    float ent = -p * __nv_logf(fmaxf(p, 1e-37f));
    if (s == 0) {
        float pl = plast / S;
        ent += -pl * __nv_logf(fmaxf(pl, 1e-37f));
    }
    #pragma unroll
    for (int o = 16; o > 0; o >>= 1) ent += __shfl_down_sync(0xffffffffu, ent, o);
    if ((s & 31) == 0) s_red[20 + (s >> 5)] = ent;
    __syncthreads();
    if (s == 0) {
        const float rent = (s_red[20] + s_red[21]) + (s_red[22] + s_red[23]);
        out[ray * 3 + 0] = r0;
        out[ray * 3 + 1] = r1;
        out[ray * 3 + 2] = r2;
        out[NRAYS * 3 + ray] = rd;
        out[NRAYS * 4 + ray] = rent;
    }
}

extern "C" void kernel_launch(void* const* d_in, const int* in_sizes, int n_in,
                              void* d_out, int out_size) {
    const float* rays   = (const float*)d_in[0];
    const float* tables = (const float*)d_in[1];
    const float* ws0    = (const float*)d_in[2];
    const float* ws1    = (const float*)d_in[3];
    const float* ws2    = (const float*)d_in[4];
    const float* wc0    = (const float*)d_in[5];
    const float* wc1    = (const float*)d_in[6];
    const float* wc2    = (const float*)d_in[7];
    const float* wc3    = (const float*)d_in[8];
    float* out = (float*)d_out;

    cudaFuncSetAttribute(nerf_fused, cudaFuncAttributeMaxDynamicSharedMemorySize, SMEM_BYTES);
    nerf_fused<<<NRAYS / RPB, NTHR, SMEM_BYTES>>>(rays, tables, ws0, ws1, ws2,
                                                  wc0, wc1, wc2, wc3, out);
}

// round 17
// speedup vs baseline: 29.0493x; 3.7370x over previous
#include <cuda_runtime.h>
#include <math.h>

#define NRAYS   16384
#define NSAMP   128
#define NSAMP_T (NRAYS * NSAMP)
#define TMASK   ((1u << 19) - 1u)

extern "C" {
__device__ float  __nv_expf(float);
__device__ float  __nv_logf(float);
__device__ double __nv_exp(double);
}

// ---- static scratch (no allocations) ----
__device__ int    g_count;
__device__ int    g_worklist[NSAMP_T];
__device__ float4 g_res[NSAMP_T];        // {col0, col1, col2, sigma}

// shared-memory weight offsets (in floats)
#define OFF_WS0 0        // 32x64
#define OFF_WS1 2048     // 64x64
#define OFF_WS2 6144     // 64x16
#define OFF_WC0 7168     // 31x64
#define OFF_WC1 9152     // 64x64
#define OFF_WC2 13248    // 64x64
#define OFF_WC3 17344    // 64x4 (padded)
#define WTOT    17600

__constant__ float c_res[16] = {16.f, 20.f, 25.f, 32.f, 40.f, 50.f, 64.f, 80.f,
                                101.f, 128.f, 161.f, 203.f, 256.f, 322.f, 406.f, 512.f};

typedef unsigned long long u64;

__device__ __forceinline__ u64 ffma2(u64 a, u64 b, u64 c) {
    u64 d;
    asm("fma.rn.f32x2 %0, %1, %2, %3;" : "=l"(d) : "l"(a), "l"(b), "l"(c));
    return d;
}
__device__ __forceinline__ u64 pack2(float v) {
    u64 d; unsigned r = __float_as_uint(v);
    asm("mov.b64 %0, {%1, %2};" : "=l"(d) : "r"(r), "r"(r));
    return d;
}
__device__ __forceinline__ void unpack2(u64 p, float& lo, float& hi) {
    asm("mov.b64 {%0, %1}, %2;" : "=f"(lo), "=f"(hi) : "l"(p));
}

// fl32(exp(-x)) for x >= 0, matching correctly-rounded fp32 exp bins.
__device__ __forceinline__ float exp32neg(float x) {
    if (x < 0.00048828125f) {
        float t = __fmul_rn(x, x);
        float c = __fmaf_rn(x, -0.16666667f, 0.5f);
        float y = __fmaf_rn(t, c, -x);
        return __fadd_rn(1.0f, y);
    }
    if (x > 104.0f) return 0.0f;
    return (float)__nv_exp(-(double)x);
}

// keep-mask computation — MUST be identical in kernels A and C.
__device__ __forceinline__ bool compute_keep(const float* __restrict__ rays,
                                             int ray, int s,
                                             float& cx, float& cy, float& cz,
                                             float& dx, float& dy, float& dz,
                                             float& z) {
    const float ox = rays[ray * 6 + 0];
    const float oy = rays[ray * 6 + 1];
    const float oz = rays[ray * 6 + 2];
    dx = rays[ray * 6 + 3];
    dy = rays[ray * 6 + 4];
    dz = rays[ray * 6 + 5];
    const float step = 4.0f / 127.0f;
    z = __fadd_rn(2.0f, __fmul_rn(step, (float)s));
    const float px = __fadd_rn(ox, __fmul_rn(dx, z));
    const float py = __fadd_rn(oy, __fmul_rn(dy, z));
    const float pz = __fadd_rn(oz, __fmul_rn(dz, z));
    cx = fminf(fmaxf(px, -1.5f), 1.5f);
    cy = fminf(fmaxf(py, -1.5f), 1.5f);
    cz = fminf(fmaxf(pz, -1.5f), 1.5f);
    return (px == cx) && (py == cy) && (pz == cz);
}

// ============ Kernel A: build worklist ============
__global__ void __launch_bounds__(256)
build_worklist(const float* __restrict__ rays)
{
    const int gid = blockIdx.x * 256 + threadIdx.x;
    const int ray = gid >> 7;
    const int s   = gid & 127;
    float cx, cy, cz, dx, dy, dz, z;
    const bool keep = compute_keep(rays, ray, s, cx, cy, cz, dx, dy, dz, z);

    const unsigned mask = __ballot_sync(0xffffffffu, keep);
    if (mask == 0) return;
    const int n = __popc(mask);
    int base;
    if ((threadIdx.x & 31) == (__ffs(mask) - 1))
        base = atomicAdd(&g_count, n);
    base = __shfl_sync(0xffffffffu, base, __ffs(mask) - 1);
    if (keep) {
        const int rank = __popc(mask & ((1u << (threadIdx.x & 31)) - 1u));
        g_worklist[base + rank] = gid;
    }
}

// 64-output layer in two 32-output half-passes.
__device__ __forceinline__ void layer64(const float* __restrict__ Wb, int n_in,
                                        const float* __restrict__ in,
                                        float* __restrict__ outv, bool relu) {
    #pragma unroll 1
    for (int h = 0; h < 2; h++) {
        u64 acc2[16];
        #pragma unroll
        for (int k = 0; k < 16; k++) acc2[k] = 0ULL;
        #pragma unroll 1
        for (int i = 0; i < n_in; i++) {
            const u64 vv = pack2(in[i]);
            const ulonglong2* wr = reinterpret_cast<const ulonglong2*>(Wb + i * 64 + h * 32);
            #pragma unroll
            for (int q = 0; q < 8; q++) {
                ulonglong2 w2 = wr[q];
                acc2[2*q]   = ffma2(vv, w2.x, acc2[2*q]);
                acc2[2*q+1] = ffma2(vv, w2.y, acc2[2*q+1]);
            }
        }
        #pragma unroll
        for (int k = 0; k < 16; k++) {
            float lo, hi;
            unpack2(acc2[k], lo, hi);
            if (relu) { lo = fmaxf(lo, 0.0f); hi = fmaxf(hi, 0.0f); }
            outv[h * 32 + 2*k]     = lo;
            outv[h * 32 + 2*k + 1] = hi;
        }
    }
}

// ============ Kernel B: dense MLP over worklist ============
__global__ void __launch_bounds__(512, 2)
mlp_dense(const float* __restrict__ rays,
          const float* __restrict__ tables,
          const float* __restrict__ ws0, const float* __restrict__ ws1,
          const float* __restrict__ ws2,
          const float* __restrict__ wc0, const float* __restrict__ wc1,
          const float* __restrict__ wc2, const float* __restrict__ wc3)
{
    __shared__ float W[WTOT];
    const int tid = threadIdx.x;
    const int total = g_count;
    const int gid0 = blockIdx.x * 512;
    if (gid0 >= total) return;

    // stage weights
    for (int i = tid; i < 2048; i += 512) W[OFF_WS0 + i] = ws0[i];
    for (int i = tid; i < 4096; i += 512) W[OFF_WS1 + i] = ws1[i];
    for (int i = tid; i < 1024; i += 512) W[OFF_WS2 + i] = ws2[i];
    for (int i = tid; i < 1984; i += 512) W[OFF_WC0 + i] = wc0[i];
    for (int i = tid; i < 4096; i += 512) W[OFF_WC1 + i] = wc1[i];
    for (int i = tid; i < 4096; i += 512) W[OFF_WC2 + i] = wc2[i];
    for (int i = tid; i < 256;  i += 512) {
        int row = i >> 2, col = i & 3;
        W[OFF_WC3 + i] = (col < 3) ? wc3[row * 3 + col] : 0.0f;
    }
    __syncthreads();

    const int idx = gid0 + tid;
    if (idx >= total) return;
    const int gid = g_worklist[idx];
    const int ray = gid >> 7;
    const int s   = gid & 127;

    float cx, cy, cz, dx, dy, dz, z;
    compute_keep(rays, ray, s, cx, cy, cz, dx, dy, dz, z);

    // ---- hash encoding ----
    float featl[32];
    #pragma unroll 1
    for (int l = 0; l < 16; l++) {
        const float res  = c_res[l];
        const float grid = 3.0f / res;

        float tx = (cx - (-1.5f)) / grid;
        float ty = (cy - (-1.5f)) / grid;
        float tz = (cz - (-1.5f)) / grid;
        float fbx = floorf(tx), fby = floorf(ty), fbz = floorf(tz);
        float vmx = fbx * grid + (-1.5f);
        float vmy = fby * grid + (-1.5f);
        float vmz = fbz * grid + (-1.5f);
        float wx = (cx - vmx) / grid;
        float wy = (cy - vmy) / grid;
        float wz = (cz - vmz) / grid;

        unsigned bx = (unsigned)(int)fbx;
        unsigned by = (unsigned)(int)fby;
        unsigned bz = (unsigned)(int)fbz;

        unsigned hx0 = bx, hx1 = bx + 1u;
        unsigned hy0 = by * 2654435761u, hy1 = (by + 1u) * 2654435761u;
        unsigned hz0 = bz * 805459861u,  hz1 = (bz + 1u) * 805459861u;

        const float2* tab = reinterpret_cast<const float2*>(tables) + ((size_t)l << 19);
        float2 e000 = __ldg(&tab[(hx0 ^ hy0 ^ hz0) & TMASK]);
        float2 e001 = __ldg(&tab[(hx0 ^ hy0 ^ hz1) & TMASK]);
        float2 e010 = __ldg(&tab[(hx0 ^ hy1 ^ hz0) & TMASK]);
        float2 e011 = __ldg(&tab[(hx0 ^ hy1 ^ hz1) & TMASK]);
        float2 e100 = __ldg(&tab[(hx1 ^ hy0 ^ hz0) & TMASK]);
        float2 e101 = __ldg(&tab[(hx1 ^ hy0 ^ hz1) & TMASK]);
        float2 e110 = __ldg(&tab[(hx1 ^ hy1 ^ hz0) & TMASK]);
        float2 e111 = __ldg(&tab[(hx1 ^ hy1 ^ hz1) & TMASK]);

        const float u0 = 1.0f - wx, u1 = 1.0f - wy, u2 = 1.0f - wz;
        float c00a = e000.x * u0 + e100.x * wx, c00b = e000.y * u0 + e100.y * wx;
        float c01a = e001.x * u0 + e101.x * wx, c01b = e001.y * u0 + e101.y * wx;
        float c10a = e010.x * u0 + e110.x * wx, c10b = e010.y * u0 + e110.y * wx;
        float c11a = e011.x * u0 + e111.x * wx, c11b = e011.y * u0 + e111.y * wx;
        float c0a = c00a * u1 + c10a * wy, c0b = c00b * u1 + c10b * wy;
        float c1a = c01a * u1 + c11a * wy, c1b = c01b * u1 + c11b * wy;
        featl[l * 2 + 0] = c0a * u2 + c1a * wz;
        featl[l * 2 + 1] = c0b * u2 + c1b * wz;
    }

    // ---- sigma MLP: 32 -> 64 -> 64 -> 16 ----
    float actl[64];
    layer64(W + OFF_WS0, 32, featl, actl, true);
    {
        float tmp[64];
        layer64(W + OFF_WS1, 64, actl, tmp, true);
        #pragma unroll
        for (int j = 0; j < 64; j++) actl[j] = tmp[j];
    }
    float h3[16];
    {
        u64 acc2[8];
        #pragma unroll
        for (int k = 0; k < 8; k++) acc2[k] = 0ULL;
        #pragma unroll 1
        for (int i = 0; i < 64; i++) {
            const u64 vv = pack2(actl[i]);
            const ulonglong2* wr = reinterpret_cast<const ulonglong2*>(W + OFF_WS2 + i * 16);
            #pragma unroll
            for (int q = 0; q < 4; q++) {
                ulonglong2 w2 = wr[q];
                acc2[2*q]   = ffma2(vv, w2.x, acc2[2*q]);
                acc2[2*q+1] = ffma2(vv, w2.y, acc2[2*q+1]);
            }
        }
        #pragma unroll
        for (int k = 0; k < 8; k++) unpack2(acc2[k], h3[2*k], h3[2*k+1]);
    }
    const float sigma = h3[0];

    // ---- SH + geo -> color input (31) ----
    float cin[31];
    {
        const float x = dx, y = dy, zc = dz;
        const float xx = x * x, yy = y * y, zz = zc * zc;
        const float xy = x * y, yz = y * zc, xz = x * zc;
        cin[0]  = 0.28209479177387814f;
        cin[1]  = -0.4886025119029199f * y;
        cin[2]  = 0.4886025119029199f * zc;
        cin[3]  = -0.4886025119029199f * x;
        cin[4]  = 1.0925484305920792f * xy;
        cin[5]  = -1.0925484305920792f * yz;
        cin[6]  = 0.31539156525252005f * (2.0f * zz - xx - yy);
        cin[7]  = -1.0925484305920792f * xz;
        cin[8]  = 0.5462742152960396f * (xx - yy);
        cin[9]  = -0.5900435899266435f * y * (3.0f * xx - yy);
        cin[10] = 2.890611442640554f * xy * zc;
        cin[11] = -0.4570457994644658f * y * (4.0f * zz - xx - yy);
        cin[12] = 0.3731763325901154f * zc * (2.0f * zz - 3.0f * xx - 3.0f * yy);
        cin[13] = -0.4570457994644658f * x * (4.0f * zz - xx - yy);
        cin[14] = 1.445305721320277f * zc * (xx - yy);
        cin[15] = -0.5900435899266435f * x * (xx - 3.0f * yy);
        #pragma unroll
        for (int j = 0; j < 15; j++) cin[16 + j] = h3[1 + j];
    }

    // ---- color MLP ----
    layer64(W + OFF_WC0, 31, cin, actl, true);
    {
        float tmp[64];
        layer64(W + OFF_WC1, 64, actl, tmp, true);
        layer64(W + OFF_WC2, 64, tmp, actl, true);
    }
    float col0 = 0.0f, col1 = 0.0f, col2 = 0.0f;
    #pragma unroll 1
    for (int i = 0; i < 64; i++) {
        const float v = actl[i];
        const float4 w4 = *reinterpret_cast<const float4*>(W + OFF_WC3 + i * 4);
        col0 = fmaf(v, w4.x, col0);
        col1 = fmaf(v, w4.y, col1);
        col2 = fmaf(v, w4.z, col2);
    }

    g_res[gid] = make_float4(col0, col1, col2, sigma);
}

// ============ Kernel C: compositing ============
#define RPB 4
#define CNT (128 * RPB)
#define RAYBUF 288

__global__ void __launch_bounds__(CNT, 4)
composite(const float* __restrict__ rays, float* __restrict__ out)
{
    __shared__ float rbs[RPB * RAYBUF];
    const int tid = threadIdx.x;
    const int r   = tid >> 7;
    const int s   = tid & 127;
    const int ray = blockIdx.x * RPB + r;

    float* rb      = rbs + r * RAYBUF;
    float* s_alpha = rb;
    float* s_w     = rb + 128;
    float* s_red   = rb + 256;

    float cx, cy, cz, dx, dy, dz, z;
    const bool keep = compute_keep(rays, ray, s, cx, cy, cz, dx, dy, dz, z);

    float sigma = 0.0f, col0 = 0.0f, col1 = 0.0f, col2 = 0.0f;
    if (keep) {
        const float4 v = g_res[ray * 128 + s];
        col0 = v.x; col1 = v.y; col2 = v.z; sigma = v.w;
    }

    const float step = 4.0f / 127.0f;
    const float znext = __fadd_rn(2.0f, __fmul_rn(step, (float)(s + 1)));
    const float n2   = __fadd_rn(__fadd_rn(__fmul_rn(dx, dx), __fmul_rn(dy, dy)),
                                 __fmul_rn(dz, dz));
    const float norm = __fsqrt_rn(n2);
    const float dz_s = __fsub_rn(znext, z);
    const float dist = (s == 127) ? __fmul_rn(1e10f, norm) : __fmul_rn(dz_s, norm);
    const float xarg = __fmul_rn(fmaxf(sigma, 0.0f), dist);
    const float alpha = __fsub_rn(1.0f, exp32neg(xarg));

    s_alpha[s] = alpha;
    __syncthreads();
    if (s == 0) {
        float t = 1.0f;
        #pragma unroll 1
        for (int i = 0; i < 128; i++) {
            float a = s_alpha[i];
            s_w[i] = __fmul_rn(a, t);
            t = __fmul_rn(t, __fadd_rn(__fsub_rn(1.0f, a), 1e-10f));
        }
    }
    __syncthreads();
    const float wgt = s_w[s];

    const float sc0 = 1.0f / (1.0f + __nv_expf(-col0));
    const float sc1 = 1.0f / (1.0f + __nv_expf(-col1));
    const float sc2 = 1.0f / (1.0f + __nv_expf(-col2));

    float v0 = wgt * sc0, v1 = wgt * sc1, v2 = wgt * sc2, v3 = wgt * z, v4 = wgt;
    #pragma unroll
    for (int o = 16; o > 0; o >>= 1) {
        v0 += __shfl_down_sync(0xffffffffu, v0, o);
        v1 += __shfl_down_sync(0xffffffffu, v1, o);
        v2 += __shfl_down_sync(0xffffffffu, v2, o);
        v3 += __shfl_down_sync(0xffffffffu, v3, o);
        v4 += __shfl_down_sync(0xffffffffu, v4, o);
    }
    if ((s & 31) == 0) {
        const int w = s >> 5;
        s_red[w]      = v0;
        s_red[4 + w]  = v1;
        s_red[8 + w]  = v2;
        s_red[12 + w] = v3;
        s_red[16 + w] = v4;
    }
    __syncthreads();
    const float r0 = (s_red[0]  + s_red[1])  + (s_red[2]  + s_red[3]);
    const float r1 = (s_red[4]  + s_red[5])  + (s_red[6]  + s_red[7]);
    const float r2 = (s_red[8]  + s_red[9])  + (s_red[10] + s_red[11]);
    const float rd = (s_red[12] + s_red[13]) + (s_red[14] + s_red[15]);
    const float sw = (s_red[16] + s_red[17]) + (s_red[18] + s_red[19]);

    const float plast = __fadd_rn(__fsub_rn(1.0f, sw), 1e-6f);
    const float S = __fadd_rn(sw, plast);
    float p = wgt / S;
    float ent = -p * __nv_logf(fmaxf(p, 1e-37f));
    if (s == 0) {
        float pl = plast / S;
        ent += -pl * __nv_logf(fmaxf(pl, 1e-37f));
    }
    #pragma unroll
    for (int o = 16; o > 0; o >>= 1) ent += __shfl_down_sync(0xffffffffu, ent, o);
    if ((s & 31) == 0) s_red[20 + (s >> 5)] = ent;
    __syncthreads();
    if (s == 0) {
        const float rent = (s_red[20] + s_red[21]) + (s_red[22] + s_red[23]);
        out[ray * 3 + 0] = r0;
        out[ray * 3 + 1] = r1;
        out[ray * 3 + 2] = r2;
        out[NRAYS * 3 + ray] = rd;
        out[NRAYS * 4 + ray] = rent;
    }
}

extern "C" void kernel_launch(void* const* d_in, const int* in_sizes, int n_in,
                              void* d_out, int out_size) {
    const float* rays   = (const float*)d_in[0];
    const float* tables = (const float*)d_in[1];
    const float* ws0    = (const float*)d_in[2];
    const float* ws1    = (const float*)d_in[3];
    const float* ws2    = (const float*)d_in[4];
    const float* wc0    = (const float*)d_in[5];
    const float* wc1    = (const float*)d_in[6];
    const float* wc2    = (const float*)d_in[7];
    const float* wc3    = (const float*)d_in[8];
    float* out = (float*)d_out;

    void* count_addr = 0;
    cudaGetSymbolAddress(&count_addr, g_count);
    cudaMemsetAsync(count_addr, 0, sizeof(int), 0);

    build_worklist<<<NSAMP_T / 256, 256>>>(rays);
    mlp_dense<<<NSAMP_T / 512, 512>>>(rays, tables, ws0, ws1, ws2, wc0, wc1, wc2, wc3);
    composite<<<NRAYS / RPB, CNT>>>(rays, out);
}